// round 16
// baseline (speedup 1.0000x reference)
#include <cuda_runtime.h>
#include <cstdint>

#define T_STEPS 16384
#define H       512
#define DYN     16
#define S       32
#define XW      (DYN + S)

#define NCTA          128
#define WARPS_PER_CTA 4
#define CTA_THREADS   (32 * WARPS_PER_CTA)   // 128
#define NREP          4     // replication factor for the published state

typedef unsigned long long u64;

// ---------------- static device scratch (allocation-free rule) ----------------
// packed (stamp<<32 | f32 bits) per h-dim, double buffered, replicated 4x.
__device__ __align__(128) u64 g_hpair[2][NREP][H];
__device__ float g_hall[(size_t)T_STEPS * H];   // 32 MB
__device__ float g_gi [(size_t)T_STEPS * H];    // sigmoid(input gate)
__device__ float g_xf [(size_t)T_STEPS * H];
__device__ float g_xg [(size_t)T_STEPS * H];
__device__ float g_xo [(size_t)T_STEPS * H];

// ---------------- helpers ----------------
__device__ __forceinline__ float sigmoid_fast(float x) {
    return __fdividef(1.0f, 1.0f + __expf(-x));
}
__device__ __forceinline__ float tanh_fast(float x) {
    float ax = fabsf(x);
    float e  = __expf(-2.0f * ax);
    float r  = __fdividef(1.0f - e, 1.0f + e);
    return copysignf(r, x);
}
// Morally-strong scalar 8B accesses: single-copy atomic, gpu scope, no L1
// staleness. Stamp rides in the same 8B word as the data -> no fences.
// LAWS (measured): weak/vector polls corrupt (R4,R7). No f32 redux on sm_103
// (R9). Best topology 128x4, NREP=4 (R11,R12). Added poll traffic regresses
// (R13). float2 staging/compute regresses (R14). R8 shape is the optimum.
__device__ __forceinline__ u64 ld_relaxed_u64(const u64* p) {
    u64 v;
    asm volatile("ld.relaxed.gpu.global.u64 %0, [%1];" : "=l"(v) : "l"(p) : "memory");
    return v;
}
__device__ __forceinline__ void st_relaxed_u64(u64* p, u64 v) {
    asm volatile("st.relaxed.gpu.global.u64 [%0], %1;" :: "l"(p), "l"(v) : "memory");
}

// ---------------- init: reset state each launch (graph replay safe) ----------
__global__ void init_kernel(const float* __restrict__ h0) {
    int i = threadIdx.x;            // 512 threads
    u64 v0 = (u64)__float_as_uint(h0[i]);     // stamp 0 | h0 bits
#pragma unroll
    for (int r = 0; r < NREP; r++) {
        g_hpair[0][r][i] = v0;
        g_hpair[1][r][i] = 0xFFFFFFFF00000000ull;   // never-matching stamp
    }
}

// ---------------- prologue: gate pre-activations, parallel over T ------------
__global__ void __launch_bounds__(512) pre_kernel(
    const float* __restrict__ x,
    const float* __restrict__ Wi,  const float* __restrict__ bi,
    const float* __restrict__ Wf1, const float* __restrict__ bf1, const float* __restrict__ bf2,
    const float* __restrict__ Wg1, const float* __restrict__ bg1, const float* __restrict__ bg2,
    const float* __restrict__ Wo1, const float* __restrict__ bo1, const float* __restrict__ bo2)
{
    const int d = threadIdx.x;      // one h-dim per thread
    float wi[S], wf[DYN], wg[DYN], wo[DYN];
#pragma unroll
    for (int s = 0; s < S; s++)   wi[s] = __ldg(&Wi[d * S + s]);
#pragma unroll
    for (int k = 0; k < DYN; k++) {
        wf[k] = __ldg(&Wf1[d * DYN + k]);
        wg[k] = __ldg(&Wg1[d * DYN + k]);
        wo[k] = __ldg(&Wo1[d * DYN + k]);
    }
    const float b_i = __ldg(&bi[d]);
    const float b_f = __ldg(&bf1[d]) + __ldg(&bf2[d]);
    const float b_g = __ldg(&bg1[d]) + __ldg(&bg2[d]);
    const float b_o = __ldg(&bo1[d]) + __ldg(&bo2[d]);

    const int nb = gridDim.x;
    const int t0 = (int)((long long)blockIdx.x       * T_STEPS / nb);
    const int t1 = (int)((long long)(blockIdx.x + 1) * T_STEPS / nb);

    for (int t = t0; t < t1; t++) {
        const float* xr = x + (size_t)t * XW;
        float ai = b_i;
#pragma unroll
        for (int s = 0; s < S; s++) ai = fmaf(__ldg(&xr[DYN + s]), wi[s], ai);
        float af = b_f, ag = b_g, ao = b_o;
#pragma unroll
        for (int k = 0; k < DYN; k++) {
            float xv = __ldg(&xr[k]);
            af = fmaf(xv, wf[k], af);
            ag = fmaf(xv, wg[k], ag);
            ao = fmaf(xv, wo[k], ao);
        }
        size_t idx = (size_t)t * H + d;
        g_gi[idx] = sigmoid_fast(ai);
        g_xf[idx] = af;
        g_xg[idx] = ag;
        g_xo[idx] = ao;
    }
}

// ---------------- the sequential scan: persistent, chip-wide -----------------
// R8's measured-best shape: 128 CTAs x 4 warps; warp owns one h-dim; stamp-in-
// data 8B exchange with scalar relaxed ld/st; 4 replicas; scalar LDS compute;
// one __syncthreads per step.
// ONLY change vs R8: ADAPTIVE POLL DROPOUT — a word whose stamp has matched
// is final for this step (stamps monotone; buffer reused only at t+2), so it
// is staged to smem immediately and dropped from subsequent poll rounds.
// Poll traffic strictly <= R8; laggard rounds get shorter.
__global__ void __launch_bounds__(CTA_THREADS, 1) scan_kernel(
    const float* __restrict__ c0,
    const float* __restrict__ Wf2,
    const float* __restrict__ Wg2,
    const float* __restrict__ Wo2)
{
    __shared__ float sh[2][H];

    const int tid  = threadIdx.x;
    const int warp = tid >> 5;
    const int lane = tid & 31;
    const int d    = blockIdx.x * WARPS_PER_CTA + warp;   // owned h-dim
    const int rep  = blockIdx.x & (NREP - 1);             // replica this CTA polls

    float wf[16], wg[16], wo[16];
#pragma unroll
    for (int j = 0; j < 16; j++) {
        int k = lane + 32 * j;
        wf[j] = __ldg(&Wf2[(size_t)d * H + k]);
        wg[j] = __ldg(&Wg2[(size_t)d * H + k]);
        wo[j] = __ldg(&Wo2[(size_t)d * H + k]);
    }

    float c = __ldg(&c0[d]);   // carried cell state (redundant across lanes)

    // gate inputs for t = 0 (broadcast loads, same addr across lanes)
    float xi = __ldg(&g_gi[d]);
    float xf = __ldg(&g_xf[d]);
    float xg = __ldg(&g_xg[d]);
    float xo = __ldg(&g_xo[d]);

    for (int t = 0; t < T_STEPS; t++) {
        const int buf = t & 1;

        // ---- adaptive poll of dims {tid,+128,+256,+384}: each word is
        //      loaded until its stamp == t, staged immediately, then dropped
        {
            const u64* hp = g_hpair[buf][rep];
            const unsigned int want = (unsigned int)t;
            bool p0 = true, p1 = true, p2 = true, p3 = true;  // pending
            do {
                if (p0) {
                    u64 a = ld_relaxed_u64(hp + tid);
                    if ((unsigned int)(a >> 32) == want) {
                        sh[buf][tid] = __uint_as_float((unsigned int)a);
                        p0 = false;
                    }
                }
                if (p1) {
                    u64 b = ld_relaxed_u64(hp + tid + 128);
                    if ((unsigned int)(b >> 32) == want) {
                        sh[buf][tid + 128] = __uint_as_float((unsigned int)b);
                        p1 = false;
                    }
                }
                if (p2) {
                    u64 cc = ld_relaxed_u64(hp + tid + 256);
                    if ((unsigned int)(cc >> 32) == want) {
                        sh[buf][tid + 256] = __uint_as_float((unsigned int)cc);
                        p2 = false;
                    }
                }
                if (p3) {
                    u64 dd = ld_relaxed_u64(hp + tid + 384);
                    if ((unsigned int)(dd >> 32) == want) {
                        sh[buf][tid + 384] = __uint_as_float((unsigned int)dd);
                        p3 = false;
                    }
                }
            } while (p0 | p1 | p2 | p3);
        }
        __syncthreads();   // the only barrier per step

        float acf = 0.f, acg = 0.f, aco = 0.f;
        const float* sb = sh[buf];
#pragma unroll
        for (int j = 0; j < 16; j++) {
            float hv = sb[lane + 32 * j];
            acf = fmaf(wf[j], hv, acf);
            acg = fmaf(wg[j], hv, acg);
            aco = fmaf(wo[j], hv, aco);
        }
        // 5-round butterfly; the 3 chains are independent so rounds overlap
#pragma unroll
        for (int s = 16; s; s >>= 1) {
            acf += __shfl_xor_sync(0xffffffffu, acf, s);
            acg += __shfl_xor_sync(0xffffffffu, acg, s);
            aco += __shfl_xor_sync(0xffffffffu, aco, s);
        }

        // all lanes compute gates redundantly (no divergence on the math)
        float f = sigmoid_fast(xf + acf);
        float g = tanh_fast(xg + acg);
        float o = sigmoid_fast(xo + aco);
        c = fmaf(f, c, xi * g);
        float hn = o * tanh_fast(c);

        // lanes 0..3 publish (stamp,value) to the 4 replicas
        if (lane < NREP) {
            u64 pk = ((u64)(unsigned int)(t + 1) << 32) | (u64)__float_as_uint(hn);
            st_relaxed_u64(&g_hpair[buf ^ 1][lane][d], pk);
        }
        if (lane == 0) {
            g_hall[(size_t)t * H + d] = hn;              // for output projection
        }

        // prefetch next step's gate inputs (off the critical path)
        if (t + 1 < T_STEPS) {
            size_t idx = (size_t)(t + 1) * H + d;
            xi = __ldg(&g_gi[idx]); xf = __ldg(&g_xf[idx]);
            xg = __ldg(&g_xg[idx]); xo = __ldg(&g_xo[idx]);
        }
    }
}

// ---------------- epilogue: out[t] = h_all[t] . Wl + bl ----------------------
__global__ void __launch_bounds__(256) proj_kernel(
    const float* __restrict__ Wl, const float* __restrict__ bl,
    float* __restrict__ out)
{
    const int warp = threadIdx.x >> 5;
    const int lane = threadIdx.x & 31;
    const int t = blockIdx.x * 8 + warp;
    float acc = 0.f;
#pragma unroll
    for (int j = 0; j < 16; j++) {
        int k = lane + 32 * j;
        acc = fmaf(g_hall[(size_t)t * H + k], __ldg(&Wl[k]), acc);
    }
#pragma unroll
    for (int s = 16; s; s >>= 1) acc += __shfl_xor_sync(0xffffffffu, acc, s);
    if (lane == 0) out[t] = acc + __ldg(&bl[0]);
}

// ---------------- launch -----------------------------------------------------
extern "C" void kernel_launch(void* const* d_in, const int* in_sizes, int n_in,
                              void* d_out, int out_size)
{
    const float* x   = (const float*)d_in[0];
    const float* h0  = (const float*)d_in[1];
    const float* c0  = (const float*)d_in[2];
    const float* Wi  = (const float*)d_in[3];
    const float* bi  = (const float*)d_in[4];
    const float* Wf1 = (const float*)d_in[5];
    const float* bf1 = (const float*)d_in[6];
    const float* Wf2 = (const float*)d_in[7];
    const float* bf2 = (const float*)d_in[8];
    const float* Wg1 = (const float*)d_in[9];
    const float* bg1 = (const float*)d_in[10];
    const float* Wg2 = (const float*)d_in[11];
    const float* bg2 = (const float*)d_in[12];
    const float* Wo1 = (const float*)d_in[13];
    const float* bo1 = (const float*)d_in[14];
    const float* Wo2 = (const float*)d_in[15];
    const float* bo2 = (const float*)d_in[16];
    const float* Wl  = (const float*)d_in[17];
    const float* bl  = (const float*)d_in[18];
    float* out = (float*)d_out;

    init_kernel<<<1, 512>>>(h0);
    pre_kernel<<<148, 512>>>(x, Wi, bi, Wf1, bf1, bf2,
                             Wg1, bg1, bg2, Wo1, bo1, bo2);
    scan_kernel<<<NCTA, CTA_THREADS>>>(c0, Wf2, Wg2, Wo2);
    proj_kernel<<<T_STEPS / 8, 256>>>(Wl, bl, out);
}

// round 17
// speedup vs baseline: 1.6927x; 1.6927x over previous
#include <cuda_runtime.h>
#include <cstdint>

#define T_STEPS 16384
#define H       512
#define DYN     16
#define S       32
#define XW      (DYN + S)

#define NCTA          128
#define WARPS_PER_CTA 4
#define CTA_THREADS   (32 * WARPS_PER_CTA)   // 128
#define NREP          4     // replication factor for the published state

typedef unsigned long long u64;

// ---------------- static device scratch (allocation-free rule) ----------------
// packed (stamp<<32 | f32 bits) per h-dim, double buffered, replicated 4x.
__device__ __align__(128) u64 g_hpair[2][NREP][H];
__device__ float g_hall[(size_t)T_STEPS * H];   // 32 MB
__device__ float g_gi [(size_t)T_STEPS * H];    // sigmoid(input gate)
__device__ float g_xf [(size_t)T_STEPS * H];
__device__ float g_xg [(size_t)T_STEPS * H];
__device__ float g_xo [(size_t)T_STEPS * H];

// ---------------- helpers ----------------
__device__ __forceinline__ float sigmoid_fast(float x) {
    return __fdividef(1.0f, 1.0f + __expf(-x));
}
__device__ __forceinline__ float tanh_fast(float x) {
    float ax = fabsf(x);
    float e  = __expf(-2.0f * ax);
    float r  = __fdividef(1.0f - e, 1.0f + e);
    return copysignf(r, x);
}
// Single-instruction MUFU tanh (sm_75+): replaces exp+div chains in the scan.
__device__ __forceinline__ float tanh_approx(float x) {
    float r;
    asm("tanh.approx.f32 %0, %1;" : "=f"(r) : "f"(x));
    return r;
}
// sigmoid via tanh identity: sigmoid(x) = 0.5*tanh(x/2) + 0.5
__device__ __forceinline__ float sigmoid_approx(float x) {
    return fmaf(0.5f, tanh_approx(0.5f * x), 0.5f);
}
// Morally-strong scalar 8B accesses: single-copy atomic, gpu scope, no L1
// staleness. Stamp rides in the same 8B word as the data -> no fences.
// LAWS (measured): weak/vector polls corrupt (R4,R7). No f32 redux on sm_103
// (R9). Best topology 128x4, NREP=4 (R11,R12). Added poll traffic regresses
// (R13). float2 staging regresses (R14). Poll MUST keep 4 loads batched,
// MLP=4 — predicated dropout serializes and badly regresses (R15).
__device__ __forceinline__ u64 ld_relaxed_u64(const u64* p) {
    u64 v;
    asm volatile("ld.relaxed.gpu.global.u64 %0, [%1];" : "=l"(v) : "l"(p) : "memory");
    return v;
}
__device__ __forceinline__ void st_relaxed_u64(u64* p, u64 v) {
    asm volatile("st.relaxed.gpu.global.u64 [%0], %1;" :: "l"(p), "l"(v) : "memory");
}

// ---------------- init: reset state each launch (graph replay safe) ----------
__global__ void init_kernel(const float* __restrict__ h0) {
    int i = threadIdx.x;            // 512 threads
    u64 v0 = (u64)__float_as_uint(h0[i]);     // stamp 0 | h0 bits
#pragma unroll
    for (int r = 0; r < NREP; r++) {
        g_hpair[0][r][i] = v0;
        g_hpair[1][r][i] = 0xFFFFFFFF00000000ull;   // never-matching stamp
    }
}

// ---------------- prologue: gate pre-activations, parallel over T ------------
// Kept on the EXACT transcendental path (off the critical path; minimizes
// the error contribution of the approx gates in the scan).
__global__ void __launch_bounds__(512) pre_kernel(
    const float* __restrict__ x,
    const float* __restrict__ Wi,  const float* __restrict__ bi,
    const float* __restrict__ Wf1, const float* __restrict__ bf1, const float* __restrict__ bf2,
    const float* __restrict__ Wg1, const float* __restrict__ bg1, const float* __restrict__ bg2,
    const float* __restrict__ Wo1, const float* __restrict__ bo1, const float* __restrict__ bo2)
{
    const int d = threadIdx.x;      // one h-dim per thread
    float wi[S], wf[DYN], wg[DYN], wo[DYN];
#pragma unroll
    for (int s = 0; s < S; s++)   wi[s] = __ldg(&Wi[d * S + s]);
#pragma unroll
    for (int k = 0; k < DYN; k++) {
        wf[k] = __ldg(&Wf1[d * DYN + k]);
        wg[k] = __ldg(&Wg1[d * DYN + k]);
        wo[k] = __ldg(&Wo1[d * DYN + k]);
    }
    const float b_i = __ldg(&bi[d]);
    const float b_f = __ldg(&bf1[d]) + __ldg(&bf2[d]);
    const float b_g = __ldg(&bg1[d]) + __ldg(&bg2[d]);
    const float b_o = __ldg(&bo1[d]) + __ldg(&bo2[d]);

    const int nb = gridDim.x;
    const int t0 = (int)((long long)blockIdx.x       * T_STEPS / nb);
    const int t1 = (int)((long long)(blockIdx.x + 1) * T_STEPS / nb);

    for (int t = t0; t < t1; t++) {
        const float* xr = x + (size_t)t * XW;
        float ai = b_i;
#pragma unroll
        for (int s = 0; s < S; s++) ai = fmaf(__ldg(&xr[DYN + s]), wi[s], ai);
        float af = b_f, ag = b_g, ao = b_o;
#pragma unroll
        for (int k = 0; k < DYN; k++) {
            float xv = __ldg(&xr[k]);
            af = fmaf(xv, wf[k], af);
            ag = fmaf(xv, wg[k], ag);
            ao = fmaf(xv, wo[k], ao);
        }
        size_t idx = (size_t)t * H + d;
        g_gi[idx] = sigmoid_fast(ai);
        g_xf[idx] = af;
        g_xg[idx] = ag;
        g_xo[idx] = ao;
    }
}

// ---------------- the sequential scan: persistent, chip-wide -----------------
// R8's measured-best shape, byte-for-byte on the sync path: 128 CTAs x 4
// warps; warp owns one h-dim; single-wave batched poll of 4 scalar relaxed
// u64 words (MLP=4); stage to smem; one __syncthreads; scalar LDS compute;
// 5-round butterfly; publish to 4 replicas.
// ONLY change vs R8: gates use single-MUFU tanh.approx (tanh direct;
// sigmoid via 0.5*tanh(x/2)+0.5) — halves MUFU ops and shortens the serial
// gate chain ~90 -> ~45 cyc.
__global__ void __launch_bounds__(CTA_THREADS, 1) scan_kernel(
    const float* __restrict__ c0,
    const float* __restrict__ Wf2,
    const float* __restrict__ Wg2,
    const float* __restrict__ Wo2)
{
    __shared__ float sh[2][H];

    const int tid  = threadIdx.x;
    const int warp = tid >> 5;
    const int lane = tid & 31;
    const int d    = blockIdx.x * WARPS_PER_CTA + warp;   // owned h-dim
    const int rep  = blockIdx.x & (NREP - 1);             // replica this CTA polls

    float wf[16], wg[16], wo[16];
#pragma unroll
    for (int j = 0; j < 16; j++) {
        int k = lane + 32 * j;
        wf[j] = __ldg(&Wf2[(size_t)d * H + k]);
        wg[j] = __ldg(&Wg2[(size_t)d * H + k]);
        wo[j] = __ldg(&Wo2[(size_t)d * H + k]);
    }

    float c = __ldg(&c0[d]);   // carried cell state (redundant across lanes)

    // gate inputs for t = 0 (broadcast loads, same addr across lanes)
    float xi = __ldg(&g_gi[d]);
    float xf = __ldg(&g_xf[d]);
    float xg = __ldg(&g_xg[d]);
    float xo = __ldg(&g_xo[d]);

    for (int t = 0; t < T_STEPS; t++) {
        const int buf = t & 1;

        // ---- R8 poll: dims {tid,+128,+256,+384}, single wave, 4 batched
        //      coalesced scalar relaxed loads (MLP=4), until all stamps == t
        {
            const u64* hp = g_hpair[buf][rep];
            const unsigned int want = (unsigned int)t;
            u64 a, b, cc, dd;
            for (;;) {
                a  = ld_relaxed_u64(hp + tid);
                b  = ld_relaxed_u64(hp + tid + 128);
                cc = ld_relaxed_u64(hp + tid + 256);
                dd = ld_relaxed_u64(hp + tid + 384);
                if ((unsigned int)(a  >> 32) == want &&
                    (unsigned int)(b  >> 32) == want &&
                    (unsigned int)(cc >> 32) == want &&
                    (unsigned int)(dd >> 32) == want) break;
            }
            sh[buf][tid      ] = __uint_as_float((unsigned int)a);
            sh[buf][tid + 128] = __uint_as_float((unsigned int)b);
            sh[buf][tid + 256] = __uint_as_float((unsigned int)cc);
            sh[buf][tid + 384] = __uint_as_float((unsigned int)dd);
        }
        __syncthreads();   // the only barrier per step

        float acf = 0.f, acg = 0.f, aco = 0.f;
        const float* sb = sh[buf];
#pragma unroll
        for (int j = 0; j < 16; j++) {
            float hv = sb[lane + 32 * j];
            acf = fmaf(wf[j], hv, acf);
            acg = fmaf(wg[j], hv, acg);
            aco = fmaf(wo[j], hv, aco);
        }
        // 5-round butterfly; the 3 chains are independent so rounds overlap
#pragma unroll
        for (int s = 16; s; s >>= 1) {
            acf += __shfl_xor_sync(0xffffffffu, acf, s);
            acg += __shfl_xor_sync(0xffffffffu, acg, s);
            aco += __shfl_xor_sync(0xffffffffu, aco, s);
        }

        // gates via single-MUFU tanh.approx (all lanes, no divergence)
        float f = sigmoid_approx(xf + acf);
        float g = tanh_approx(xg + acg);
        float o = sigmoid_approx(xo + aco);
        c = fmaf(f, c, xi * g);
        float hn = o * tanh_approx(c);

        // lanes 0..3 publish (stamp,value) to the 4 replicas
        if (lane < NREP) {
            u64 pk = ((u64)(unsigned int)(t + 1) << 32) | (u64)__float_as_uint(hn);
            st_relaxed_u64(&g_hpair[buf ^ 1][lane][d], pk);
        }
        if (lane == 0) {
            g_hall[(size_t)t * H + d] = hn;              // for output projection
        }

        // prefetch next step's gate inputs (off the critical path)
        if (t + 1 < T_STEPS) {
            size_t idx = (size_t)(t + 1) * H + d;
            xi = __ldg(&g_gi[idx]); xf = __ldg(&g_xf[idx]);
            xg = __ldg(&g_xg[idx]); xo = __ldg(&g_xo[idx]);
        }
    }
}

// ---------------- epilogue: out[t] = h_all[t] . Wl + bl ----------------------
__global__ void __launch_bounds__(256) proj_kernel(
    const float* __restrict__ Wl, const float* __restrict__ bl,
    float* __restrict__ out)
{
    const int warp = threadIdx.x >> 5;
    const int lane = threadIdx.x & 31;
    const int t = blockIdx.x * 8 + warp;
    float acc = 0.f;
#pragma unroll
    for (int j = 0; j < 16; j++) {
        int k = lane + 32 * j;
        acc = fmaf(g_hall[(size_t)t * H + k], __ldg(&Wl[k]), acc);
    }
#pragma unroll
    for (int s = 16; s; s >>= 1) acc += __shfl_xor_sync(0xffffffffu, acc, s);
    if (lane == 0) out[t] = acc + __ldg(&bl[0]);
}

// ---------------- launch -----------------------------------------------------
extern "C" void kernel_launch(void* const* d_in, const int* in_sizes, int n_in,
                              void* d_out, int out_size)
{
    const float* x   = (const float*)d_in[0];
    const float* h0  = (const float*)d_in[1];
    const float* c0  = (const float*)d_in[2];
    const float* Wi  = (const float*)d_in[3];
    const float* bi  = (const float*)d_in[4];
    const float* Wf1 = (const float*)d_in[5];
    const float* bf1 = (const float*)d_in[6];
    const float* Wf2 = (const float*)d_in[7];
    const float* bf2 = (const float*)d_in[8];
    const float* Wg1 = (const float*)d_in[9];
    const float* bg1 = (const float*)d_in[10];
    const float* Wg2 = (const float*)d_in[11];
    const float* bg2 = (const float*)d_in[12];
    const float* Wo1 = (const float*)d_in[13];
    const float* bo1 = (const float*)d_in[14];
    const float* Wo2 = (const float*)d_in[15];
    const float* bo2 = (const float*)d_in[16];
    const float* Wl  = (const float*)d_in[17];
    const float* bl  = (const float*)d_in[18];
    float* out = (float*)d_out;

    init_kernel<<<1, 512>>>(h0);
    pre_kernel<<<148, 512>>>(x, Wi, bi, Wf1, bf1, bf2,
                             Wg1, bg1, bg2, Wo1, bo1, bo2);
    scan_kernel<<<NCTA, CTA_THREADS>>>(c0, Wf2, Wg2, Wo2);
    proj_kernel<<<T_STEPS / 8, 256>>>(Wl, bl, out);
}